// round 1
// baseline (speedup 1.0000x reference)
#include <cuda_runtime.h>
#include <stdint.h>

// Problem constants (fixed shapes from reference)
#define Kc   512               // codebook size
#define Dc   8                 // embedding dim / channels
#define Sc   110592            // 48*48*48
#define Bc   2                 // batch
#define Nc   (Bc * Sc)         // 221184 voxels
#define TPB  256               // threads per block
#define VPB  256               // voxels per block
#define NBLK (Nc / VPB)        // 864 blocks
#define O_OUT 1                // out tensor offset (after scalar loss)
#define O_ENC (1 + Nc * Dc)    // encodings offset = 1769473
#define TILE_ENC (VPB * Kc)    // 131072 floats per block's encodings tile

__device__ float g_sum;

__global__ void vq_init_kernel() { g_sum = 0.0f; }

__global__ __launch_bounds__(TPB) void vq_main_kernel(
    const float* __restrict__ x,
    const float* __restrict__ ew,
    float* __restrict__ out)
{
    __shared__ float4 sE[Kc * 2];   // codebook: 2 float4 per entry
    __shared__ float  sE2[Kc];      // per-entry sum of squares
    __shared__ float  sRed[TPB / 32];

    const int tid = threadIdx.x;

    // ---- Phase 0: zero this block's encodings tile (coalesced, fire & forget).
    // These stores drain to DRAM while the FFMA argmin loop below executes.
    {
        float* t0 = out + O_ENC + (size_t)blockIdx.x * TILE_ENC;
        // O_ENC is odd -> tile base is 4B-aligned only; peel to 16B alignment.
        unsigned head = (unsigned)((16u - (unsigned)(((uintptr_t)t0) & 15u)) & 15u) >> 2;
        if (tid < (int)head) t0[tid] = 0.0f;
        float4 z4 = make_float4(0.f, 0.f, 0.f, 0.f);
        float4* v = (float4*)(t0 + head);
        int nv = (TILE_ENC - (int)head) >> 2;
        for (int i = tid; i < nv; i += TPB) v[i] = z4;
        int done = (int)head + (nv << 2);
        if (tid < TILE_ENC - done) t0[done + tid] = 0.0f;
    }

    // ---- Phase 1: load codebook into shared
    {
        const float4* src = (const float4*)ew;   // 512*8 floats = 1024 float4
        for (int i = tid; i < Kc * 2; i += TPB) sE[i] = src[i];
    }
    __syncthreads();

    // ---- Phase 2: per-entry sum of squares, sequential fp32 (match jnp.sum(e**2))
    for (int k = tid; k < Kc; k += TPB) {
        float4 a = sE[2 * k], b = sE[2 * k + 1];
        float s = __fmul_rn(a.x, a.x);
        s = __fadd_rn(s, __fmul_rn(a.y, a.y));
        s = __fadd_rn(s, __fmul_rn(a.z, a.z));
        s = __fadd_rn(s, __fmul_rn(a.w, a.w));
        s = __fadd_rn(s, __fmul_rn(b.x, b.x));
        s = __fadd_rn(s, __fmul_rn(b.y, b.y));
        s = __fadd_rn(s, __fmul_rn(b.z, b.z));
        s = __fadd_rn(s, __fmul_rn(b.w, b.w));
        sE2[k] = s;
    }
    __syncthreads();

    // ---- Phase 3: load this thread's voxel (8 strided, warp-coalesced loads)
    const int n = blockIdx.x * VPB + tid;
    const int b = (n >= Sc) ? 1 : 0;
    const int s = n - b * Sc;
    const float* xp = x + (size_t)b * (Dc * Sc) + s;
    float xv[8];
#pragma unroll
    for (int c = 0; c < 8; c++) xv[c] = xp[(size_t)c * Sc];

    // sum(x^2): square then sequential add (match reference rounding chain)
    float sumx2 = __fmul_rn(xv[0], xv[0]);
#pragma unroll
    for (int c = 1; c < 8; c++) sumx2 = __fadd_rn(sumx2, __fmul_rn(xv[c], xv[c]));

    // ---- Phase 4: argmin over 512 codebook entries.
    // d_k = round(round(sumx2 + sume2_k) - 2*dot_k)  -- replicates reference
    // quantization to ulp(~8) so near-ties break identically (lowest index wins).
    float best = 3.4e38f;
    int   bi   = 0;
#pragma unroll 4
    for (int k = 0; k < Kc; k++) {
        float4 a = sE[2 * k], e1 = sE[2 * k + 1];
        float t = __fmul_rn(xv[0], a.x);
        t = __fmaf_rn(xv[1], a.y, t);
        t = __fmaf_rn(xv[2], a.z, t);
        t = __fmaf_rn(xv[3], a.w, t);
        t = __fmaf_rn(xv[4], e1.x, t);
        t = __fmaf_rn(xv[5], e1.y, t);
        t = __fmaf_rn(xv[6], e1.z, t);
        t = __fmaf_rn(xv[7], e1.w, t);
        float d = __fadd_rn(sumx2, sE2[k]);
        d = __fmaf_rn(-2.0f, t, d);          // single rounding, == (s - 2t)
        if (d < best) { best = d; bi = k; }  // strict <: lowest index on ties
    }

    // ---- Phase 5: write quantized output (forward STE == quantized values)
    float4 qa = sE[2 * bi], qb = sE[2 * bi + 1];
    float q[8] = {qa.x, qa.y, qa.z, qa.w, qb.x, qb.y, qb.z, qb.w};
    float* op = out + O_OUT + (size_t)b * (Dc * Sc) + s;
    float acc = 0.0f;
#pragma unroll
    for (int c = 0; c < 8; c++) {
        op[(size_t)c * Sc] = q[c];
        float dd = xv[c] - q[c];
        acc = fmaf(dd, dd, acc);
    }

    // Zero phase for this block's tile completed before the earlier
    // __syncthreads() (which carries block-level memory fence semantics),
    // so the scatter of 1.0 cannot be overwritten by a zero.
    out[O_ENC + (size_t)n * Kc + bi] = 1.0f;

    // ---- Phase 6: block-reduce squared error, one atomic per block
#pragma unroll
    for (int o = 16; o > 0; o >>= 1) acc += __shfl_down_sync(0xFFFFFFFFu, acc, o);
    if ((tid & 31) == 0) sRed[tid >> 5] = acc;
    __syncthreads();
    if (tid < (TPB / 32)) {
        float v = sRed[tid];
#pragma unroll
        for (int o = (TPB / 64); o > 0; o >>= 1) v += __shfl_down_sync(0xFFu, v, o);
        if (tid == 0) atomicAdd(&g_sum, v);
    }
}

__global__ void vq_fin_kernel(float* __restrict__ out)
{
    float m = g_sum / (float)((size_t)Nc * Dc);
    m = fminf(fmaxf(m, 0.0f), 10.0f);
    // loss = q_latent + 0.25*e_latent; both clip to the same mean forward
    out[0] = 1.25f * m;
}

extern "C" void kernel_launch(void* const* d_in, const int* in_sizes, int n_in,
                              void* d_out, int out_size)
{
    const float* x  = (const float*)d_in[0];
    const float* ew = (const float*)d_in[1];
    float* out = (float*)d_out;

    vq_init_kernel<<<1, 1>>>();
    vq_main_kernel<<<NBLK, TPB>>>(x, ew, out);
    vq_fin_kernel<<<1, 1>>>(out);
}

// round 2
// speedup vs baseline: 1.4252x; 1.4252x over previous
#include <cuda_runtime.h>
#include <stdint.h>

// Problem constants (fixed shapes from reference)
#define Kc   512               // codebook size
#define Dc   8                 // embedding dim / channels
#define Sc   110592            // 48*48*48
#define Bc   2                 // batch
#define Nc   (Bc * Sc)         // 221184 voxels
#define TPB  256               // threads per block
#define VPB  512               // voxels per block (2 per thread)
#define NBLK (Nc / VPB)        // 432 blocks  (one wave @ 3 CTAs/SM on 148 SMs)
#define NPAIR 256              // codebook pairs (Kc/2)
#define O_OUT 1                // out tensor offset (after scalar loss)
#define O_ENC (1 + Nc * Dc)    // encodings offset = 1769473
#define TILE_ENC (VPB * Kc)    // 262144 floats per block's encodings tile

__device__ float g_bsum[NBLK];

// ---- packed f32x2 helpers (Blackwell FFMA2 path; per-lane rounding == scalar) ----
__device__ __forceinline__ unsigned long long pk2(float lo, float hi) {
    unsigned long long r;
    asm("mov.b64 %0, {%1, %2};" : "=l"(r) : "f"(lo), "f"(hi));
    return r;
}
__device__ __forceinline__ unsigned long long mul2(unsigned long long a, unsigned long long b) {
    unsigned long long d;
    asm("mul.rn.f32x2 %0, %1, %2;" : "=l"(d) : "l"(a), "l"(b));
    return d;
}
__device__ __forceinline__ unsigned long long add2(unsigned long long a, unsigned long long b) {
    unsigned long long d;
    asm("add.rn.f32x2 %0, %1, %2;" : "=l"(d) : "l"(a), "l"(b));
    return d;
}
__device__ __forceinline__ unsigned long long fma2(unsigned long long a, unsigned long long b, unsigned long long c) {
    unsigned long long d;
    asm("fma.rn.f32x2 %0, %1, %2, %3;" : "=l"(d) : "l"(a), "l"(b), "l"(c));
    return d;
}
__device__ __forceinline__ void upk2(unsigned long long v, float& lo, float& hi) {
    asm("mov.b64 {%0, %1}, %2;" : "=f"(lo), "=f"(hi) : "l"(v));
}

__global__ __launch_bounds__(TPB, 3) void vq_main_kernel(
    const float* __restrict__ x,
    const float* __restrict__ ew,
    float* __restrict__ out)
{
    // Pair-interleaved codebook: for pair p, coord c: (e[2p][c], e[2p+1][c]).
    // Stored as ulonglong2[p*4+j] = { pack(c=2j), pack(c=2j+1) }.
    __shared__ ulonglong2 sEp[NPAIR * 4];   // 16 KB
    __shared__ float      sE2[Kc];          // 2 KB, pairs adjacent (2p, 2p+1)
    __shared__ float      sRed[TPB / 32];

    const int tid = threadIdx.x;

    // ---- Phase 1a: build pair-packed codebook in shared
    {
        float* sf = (float*)sEp;
        for (int idx = tid; idx < NPAIR * Dc; idx += TPB) {   // 2048 float2 slots
            int p = idx >> 3, c = idx & 7;
            float lo = ew[(2 * p) * Dc + c];
            float hi = ew[(2 * p + 1) * Dc + c];
            int base = p * 16 + (c >> 1) * 4 + (c & 1) * 2;
            sf[base]     = lo;
            sf[base + 1] = hi;
        }
    }
    // ---- Phase 1b: per-entry sum of squares, sequential fp32 (match jnp.sum(e**2))
    for (int k = tid; k < Kc; k += TPB) {
        float4 a = *(const float4*)(ew + (size_t)k * Dc);
        float4 b = *(const float4*)(ew + (size_t)k * Dc + 4);
        float s = __fmul_rn(a.x, a.x);
        s = __fadd_rn(s, __fmul_rn(a.y, a.y));
        s = __fadd_rn(s, __fmul_rn(a.z, a.z));
        s = __fadd_rn(s, __fmul_rn(a.w, a.w));
        s = __fadd_rn(s, __fmul_rn(b.x, b.x));
        s = __fadd_rn(s, __fmul_rn(b.y, b.y));
        s = __fadd_rn(s, __fmul_rn(b.z, b.z));
        s = __fadd_rn(s, __fmul_rn(b.w, b.w));
        sE2[k] = s;
    }
    __syncthreads();

    // ---- Phase 2: load this thread's two voxels (strided, warp-coalesced)
    const int bb = (blockIdx.x * VPB) >= Sc ? 1 : 0;   // batch boundary is block-aligned
    const int n0 = blockIdx.x * VPB + tid;
    const int n1 = n0 + TPB;
    const int sA = n0 - bb * Sc;
    const int sB = n1 - bb * Sc;
    const float* xbase = x + (size_t)bb * (Dc * Sc);

    float xA[8], xB[8];
#pragma unroll
    for (int c = 0; c < 8; c++) {
        xA[c] = xbase[(size_t)c * Sc + sA];
        xB[c] = xbase[(size_t)c * Sc + sB];
    }
    unsigned long long xa[8], xb[8];
#pragma unroll
    for (int c = 0; c < 8; c++) { xa[c] = pk2(xA[c], xA[c]); xb[c] = pk2(xB[c], xB[c]); }

    // sum(x^2): square then sequential add (match reference rounding chain)
    float s2A = __fmul_rn(xA[0], xA[0]);
    float s2B = __fmul_rn(xB[0], xB[0]);
#pragma unroll
    for (int c = 1; c < 8; c++) {
        s2A = __fadd_rn(s2A, __fmul_rn(xA[c], xA[c]));
        s2B = __fadd_rn(s2B, __fmul_rn(xB[c], xB[c]));
    }
    const unsigned long long sA2 = pk2(s2A, s2A);
    const unsigned long long sB2 = pk2(s2B, s2B);
    const unsigned long long n2  = pk2(-2.0f, -2.0f);

    // ---- Phase 3: zero-tile setup (stores interleaved with argmin below)
    float* t0 = out + O_ENC + (size_t)blockIdx.x * TILE_ENC;
    const int head = (int)(((16u - (unsigned)(((uintptr_t)t0) & 15u)) & 15u) >> 2);
    if (tid < head) t0[tid] = 0.0f;
    float4* zv = (float4*)(t0 + head);
    const int nv = (TILE_ENC - head) >> 2;
    const float4 z4 = make_float4(0.f, 0.f, 0.f, 0.f);

    // ---- Phase 4: argmin over 256 pairs; one zero STG.128 per iteration.
    // Per lane: d = fma(-2, dot, add(sumx2, sE2[k])) with the exact sequential
    // dot chain -> bit-identical distances to the reference's rounding, so
    // near-ties break the same way (strict <, lowest index wins).
    float bestA = 3.4e38f, bestB = 3.4e38f;
    int   biA = 0, biB = 0;

#pragma unroll 2
    for (int p = 0; p < NPAIR; p++) {
        int zi = tid + (p << 8);
        if (zi < nv) zv[zi] = z4;     // streams to DRAM while FMAs run

        ulonglong2 v0 = sEp[p * 4 + 0];
        ulonglong2 v1 = sEp[p * 4 + 1];
        ulonglong2 v2 = sEp[p * 4 + 2];
        ulonglong2 v3 = sEp[p * 4 + 3];

        unsigned long long tA = mul2(xa[0], v0.x);
        unsigned long long tB = mul2(xb[0], v0.x);
        tA = fma2(xa[1], v0.y, tA);  tB = fma2(xb[1], v0.y, tB);
        tA = fma2(xa[2], v1.x, tA);  tB = fma2(xb[2], v1.x, tB);
        tA = fma2(xa[3], v1.y, tA);  tB = fma2(xb[3], v1.y, tB);
        tA = fma2(xa[4], v2.x, tA);  tB = fma2(xb[4], v2.x, tB);
        tA = fma2(xa[5], v2.y, tA);  tB = fma2(xb[5], v2.y, tB);
        tA = fma2(xa[6], v3.x, tA);  tB = fma2(xb[6], v3.x, tB);
        tA = fma2(xa[7], v3.y, tA);  tB = fma2(xb[7], v3.y, tB);

        unsigned long long e2 = *(const unsigned long long*)&sE2[2 * p];
        unsigned long long dA = fma2(n2, tA, add2(sA2, e2));
        unsigned long long dB = fma2(n2, tB, add2(sB2, e2));

        float dAl, dAh, dBl, dBh;
        upk2(dA, dAl, dAh);
        upk2(dB, dBl, dBh);
        if (dAl < bestA) { bestA = dAl; biA = 2 * p; }
        if (dAh < bestA) { bestA = dAh; biA = 2 * p + 1; }
        if (dBl < bestB) { bestB = dBl; biB = 2 * p; }
        if (dBh < bestB) { bestB = dBh; biB = 2 * p + 1; }
    }
    // tail of the zero tile (at most 3 floats)
    {
        int done = head + (nv << 2);
        if (tid < TILE_ENC - done) t0[done + tid] = 0.0f;
    }

    // ---- Phase 5: gather chosen entries, write quantized out, accumulate MSE
    const float* sf = (const float*)sEp;
    float acc = 0.0f;
    {
        int p = biA >> 1, l = biA & 1;
        float* op = out + O_OUT + (size_t)bb * (Dc * Sc) + sA;
#pragma unroll
        for (int c = 0; c < 8; c++) {
            float q = sf[p * 16 + (c >> 1) * 4 + (c & 1) * 2 + l];
            op[(size_t)c * Sc] = q;
            float dd = xA[c] - q;
            acc = fmaf(dd, dd, acc);
        }
    }
    {
        int p = biB >> 1, l = biB & 1;
        float* op = out + O_OUT + (size_t)bb * (Dc * Sc) + sB;
#pragma unroll
        for (int c = 0; c < 8; c++) {
            float q = sf[p * 16 + (c >> 1) * 4 + (c & 1) * 2 + l];
            op[(size_t)c * Sc] = q;
            float dd = xB[c] - q;
            acc = fmaf(dd, dd, acc);
        }
    }

    // Order all zero stores of the block before the 1.0 scatters
    __syncthreads();
    out[O_ENC + (size_t)n0 * Kc + biA] = 1.0f;
    out[O_ENC + (size_t)n1 * Kc + biB] = 1.0f;

    // ---- Phase 6: block-reduce squared error, one slot per block (no atomics)
#pragma unroll
    for (int o = 16; o > 0; o >>= 1) acc += __shfl_down_sync(0xFFFFFFFFu, acc, o);
    if ((tid & 31) == 0) sRed[tid >> 5] = acc;
    __syncthreads();
    if (tid < (TPB / 32)) {
        float v = sRed[tid];
#pragma unroll
        for (int o = (TPB / 64); o > 0; o >>= 1) v += __shfl_down_sync(0xFFu, v, o);
        if (tid == 0) g_bsum[blockIdx.x] = v;
    }
}

__global__ void vq_fin_kernel(float* __restrict__ out)
{
    __shared__ float sRed[8];
    int tid = threadIdx.x;
    float s = 0.0f;
    for (int i = tid; i < NBLK; i += 256) s += g_bsum[i];
#pragma unroll
    for (int o = 16; o > 0; o >>= 1) s += __shfl_down_sync(0xFFFFFFFFu, s, o);
    if ((tid & 31) == 0) sRed[tid >> 5] = s;
    __syncthreads();
    if (tid < 8) {
        float v = sRed[tid];
#pragma unroll
        for (int o = 4; o > 0; o >>= 1) v += __shfl_down_sync(0xFFu, v, o);
        if (tid == 0) {
            float m = v / (float)((size_t)Nc * Dc);
            m = fminf(fmaxf(m, 0.0f), 10.0f);
            out[0] = 1.25f * m;   // q_latent + BETA * e_latent (identical forward)
        }
    }
}

extern "C" void kernel_launch(void* const* d_in, const int* in_sizes, int n_in,
                              void* d_out, int out_size)
{
    const float* x  = (const float*)d_in[0];
    const float* ew = (const float*)d_in[1];
    float* out = (float*)d_out;

    vq_main_kernel<<<NBLK, TPB>>>(x, ew, out);
    vq_fin_kernel<<<1, 256>>>(out);
}

// round 4
// speedup vs baseline: 1.4328x; 1.0053x over previous
#include <cuda_runtime.h>
#include <stdint.h>

// Problem constants (fixed shapes from reference)
#define Kc   512               // codebook size
#define Dc   8                 // embedding dim / channels
#define Sc   110592            // 48*48*48
#define Bc   2                 // batch
#define Nc   (Bc * Sc)         // 221184 voxels
#define TPB  256               // threads per block
#define VPB  512               // voxels per block (2 per thread)
#define NBLK (Nc / VPB)        // 432 blocks  (one wave @ 3 CTAs/SM)
#define NPAIR 256              // codebook pairs (Kc/2)
#define O_OUT 1                // out tensor offset (after scalar loss)
#define O_ENC (1 + Nc * Dc)    // encodings offset = 1769473
#define TILE_ENC (VPB * Kc)    // 262144 floats per block's encodings tile
#define ZBUF_BYTES 16384       // smem zero buffer for TMA bulk stores

__device__ float    g_sum   = 0.0f;   // reset by last block each run
__device__ unsigned g_count = 0u;

// ---- packed f32x2 helpers (Blackwell FFMA2; per-lane rounding == scalar) ----
__device__ __forceinline__ unsigned long long pk2(float lo, float hi) {
    unsigned long long r;
    asm("mov.b64 %0, {%1, %2};" : "=l"(r) : "f"(lo), "f"(hi));
    return r;
}
__device__ __forceinline__ unsigned long long mul2(unsigned long long a, unsigned long long b) {
    unsigned long long d;
    asm("mul.rn.f32x2 %0, %1, %2;" : "=l"(d) : "l"(a), "l"(b));
    return d;
}
__device__ __forceinline__ unsigned long long add2(unsigned long long a, unsigned long long b) {
    unsigned long long d;
    asm("add.rn.f32x2 %0, %1, %2;" : "=l"(d) : "l"(a), "l"(b));
    return d;
}
__device__ __forceinline__ unsigned long long fma2(unsigned long long a, unsigned long long b, unsigned long long c) {
    unsigned long long d;
    asm("fma.rn.f32x2 %0, %1, %2, %3;" : "=l"(d) : "l"(a), "l"(b), "l"(c));
    return d;
}
__device__ __forceinline__ void upk2(unsigned long long v, float& lo, float& hi) {
    asm("mov.b64 {%0, %1}, %2;" : "=f"(lo), "=f"(hi) : "l"(v));
}
__device__ __forceinline__ uint32_t smem_u32(const void* p) {
    uint32_t a;
    asm("{ .reg .u64 t; cvta.to.shared.u64 t, %1; cvt.u32.u64 %0, t; }" : "=r"(a) : "l"(p));
    return a;
}

__global__ __launch_bounds__(TPB, 3) void vq_main_kernel(
    const float* __restrict__ x,
    const float* __restrict__ ew,
    float* __restrict__ out)
{
    // Pair-interleaved codebook: pair p, coord c -> (e[2p][c], e[2p+1][c]).
    __shared__ ulonglong2 sEp[NPAIR * 4];          // 16 KB
    __shared__ float      sE2[Kc];                 // 2 KB
    __shared__ float4     sZero[ZBUF_BYTES / 16];  // 16 KB of zeros (TMA source)
    __shared__ float      sRed[TPB / 32];
    __shared__ int        sLast;

    const int tid = threadIdx.x;

    // ---- Phase 0: fill zero buffer (TMA source)
    {
        float4 z4 = make_float4(0.f, 0.f, 0.f, 0.f);
        for (int i = tid; i < ZBUF_BYTES / 16; i += TPB) sZero[i] = z4;
    }

    // ---- Phase 1a: build pair-packed codebook in shared
    {
        float* sf = (float*)sEp;
        for (int idx = tid; idx < NPAIR * Dc; idx += TPB) {
            int p = idx >> 3, c = idx & 7;
            float lo = ew[(2 * p) * Dc + c];
            float hi = ew[(2 * p + 1) * Dc + c];
            int base = p * 16 + (c >> 1) * 4 + (c & 1) * 2;
            sf[base]     = lo;
            sf[base + 1] = hi;
        }
    }
    // ---- Phase 1b: per-entry sum of squares, sequential fp32 (match jnp.sum(e**2))
    for (int k = tid; k < Kc; k += TPB) {
        float4 a = *(const float4*)(ew + (size_t)k * Dc);
        float4 b = *(const float4*)(ew + (size_t)k * Dc + 4);
        float s = __fmul_rn(a.x, a.x);
        s = __fadd_rn(s, __fmul_rn(a.y, a.y));
        s = __fadd_rn(s, __fmul_rn(a.z, a.z));
        s = __fadd_rn(s, __fmul_rn(a.w, a.w));
        s = __fadd_rn(s, __fmul_rn(b.x, b.x));
        s = __fadd_rn(s, __fmul_rn(b.y, b.y));
        s = __fadd_rn(s, __fmul_rn(b.z, b.z));
        s = __fadd_rn(s, __fmul_rn(b.w, b.w));
        sE2[k] = s;
    }
    // Make the generic-proxy smem zero writes visible to the async (TMA) proxy.
    asm volatile("fence.proxy.async.shared::cta;" ::: "memory");
    __syncthreads();

    // ---- Phase 2: launch the zero-fill of this block's encodings tile via TMA.
    // 64 x 16KB bulk copies, spread over the first 8 lanes of warp 0 (8 each).
    float* t0 = out + O_ENC + (size_t)blockIdx.x * TILE_ENC;
    const int head = (int)(((16u - (unsigned)(((uintptr_t)t0) & 15u)) & 15u) >> 2);
    if (tid < head) t0[tid] = 0.0f;                     // peel to 16B alignment
    const int nfl = (TILE_ENC - head) & ~3;             // floats covered by TMA
    const size_t nbytes = (size_t)nfl * 4;
    if (tid < 8) {
        uint32_t s_addr = smem_u32(sZero);
        char* g = (char*)(t0 + head);
        for (size_t off = (size_t)tid * ZBUF_BYTES; off < nbytes;
             off += (size_t)8 * ZBUF_BYTES) {
            unsigned sz = (unsigned)((nbytes - off) < (size_t)ZBUF_BYTES
                                     ? (nbytes - off) : (size_t)ZBUF_BYTES);
            asm volatile(
                "cp.async.bulk.global.shared::cta.bulk_group [%0], [%1], %2;"
                :: "l"(g + off), "r"(s_addr), "r"(sz) : "memory");
        }
        asm volatile("cp.async.bulk.commit_group;" ::: "memory");
    }
    {   // tail floats not covered by 16B-granular TMA
        int done = head + nfl;
        if (tid < TILE_ENC - done) t0[done + tid] = 0.0f;
    }

    // ---- Phase 3: load this thread's two voxels (strided, warp-coalesced)
    const int bb = (blockIdx.x * VPB) >= Sc ? 1 : 0;    // batch split is block-aligned
    const int n0 = blockIdx.x * VPB + tid;
    const int n1 = n0 + TPB;
    const int sA = n0 - bb * Sc;
    const int sB = n1 - bb * Sc;
    const float* xbase = x + (size_t)bb * (Dc * Sc);

    float xA[8], xB[8];
#pragma unroll
    for (int c = 0; c < 8; c++) {
        xA[c] = xbase[(size_t)c * Sc + sA];
        xB[c] = xbase[(size_t)c * Sc + sB];
    }
    unsigned long long xa[8], xb[8];
#pragma unroll
    for (int c = 0; c < 8; c++) { xa[c] = pk2(xA[c], xA[c]); xb[c] = pk2(xB[c], xB[c]); }

    float s2A = __fmul_rn(xA[0], xA[0]);
    float s2B = __fmul_rn(xB[0], xB[0]);
#pragma unroll
    for (int c = 1; c < 8; c++) {
        s2A = __fadd_rn(s2A, __fmul_rn(xA[c], xA[c]));
        s2B = __fadd_rn(s2B, __fmul_rn(xB[c], xB[c]));
    }
    const unsigned long long sA2 = pk2(s2A, s2A);
    const unsigned long long sB2 = pk2(s2B, s2B);
    const unsigned long long n2  = pk2(-2.0f, -2.0f);

    // ---- Phase 4: argmin over 256 pairs (pure FMA loop; TMA drains under it).
    // Per lane: d = fma(-2, dot, add(sumx2, sE2[k])) — bit-identical to the
    // reference rounding, strict < gives lowest index on ties.
    float bestA = 3.4e38f, bestB = 3.4e38f;
    int   biA = 0, biB = 0;

#pragma unroll 2
    for (int p = 0; p < NPAIR; p++) {
        ulonglong2 v0 = sEp[p * 4 + 0];
        ulonglong2 v1 = sEp[p * 4 + 1];
        ulonglong2 v2 = sEp[p * 4 + 2];
        ulonglong2 v3 = sEp[p * 4 + 3];

        unsigned long long tA = mul2(xa[0], v0.x);
        unsigned long long tB = mul2(xb[0], v0.x);
        tA = fma2(xa[1], v0.y, tA);  tB = fma2(xb[1], v0.y, tB);
        tA = fma2(xa[2], v1.x, tA);  tB = fma2(xb[2], v1.x, tB);
        tA = fma2(xa[3], v1.y, tA);  tB = fma2(xb[3], v1.y, tB);
        tA = fma2(xa[4], v2.x, tA);  tB = fma2(xb[4], v2.x, tB);
        tA = fma2(xa[5], v2.y, tA);  tB = fma2(xb[5], v2.y, tB);
        tA = fma2(xa[6], v3.x, tA);  tB = fma2(xb[6], v3.x, tB);
        tA = fma2(xa[7], v3.y, tA);  tB = fma2(xb[7], v3.y, tB);

        unsigned long long e2 = *(const unsigned long long*)&sE2[2 * p];
        unsigned long long dA = fma2(n2, tA, add2(sA2, e2));
        unsigned long long dB = fma2(n2, tB, add2(sB2, e2));

        float dAl, dAh, dBl, dBh;
        upk2(dA, dAl, dAh);
        upk2(dB, dBl, dBh);
        if (dAl < bestA) { bestA = dAl; biA = 2 * p; }
        if (dAh < bestA) { bestA = dAh; biA = 2 * p + 1; }
        if (dBl < bestB) { bestB = dBl; biB = 2 * p; }
        if (dBh < bestB) { bestB = dBh; biB = 2 * p + 1; }
    }

    // ---- Phase 5: gather chosen entries, write quantized out, accumulate MSE
    const float* sf = (const float*)sEp;
    float acc = 0.0f;
    {
        int p = biA >> 1, l = biA & 1;
        float* op = out + O_OUT + (size_t)bb * (Dc * Sc) + sA;
#pragma unroll
        for (int c = 0; c < 8; c++) {
            float q = sf[p * 16 + (c >> 1) * 4 + (c & 1) * 2 + l];
            op[(size_t)c * Sc] = q;
            float dd = xA[c] - q;
            acc = fmaf(dd, dd, acc);
        }
    }
    {
        int p = biB >> 1, l = biB & 1;
        float* op = out + O_OUT + (size_t)bb * (Dc * Sc) + sB;
#pragma unroll
        for (int c = 0; c < 8; c++) {
            float q = sf[p * 16 + (c >> 1) * 4 + (c & 1) * 2 + l];
            op[(size_t)c * Sc] = q;
            float dd = xB[c] - q;
            acc = fmaf(dd, dd, acc);
        }
    }

    // ---- Phase 6: wait for the TMA zero-fill, then scatter the 1.0s (WAW safe)
    if (tid < 8) asm volatile("cp.async.bulk.wait_group 0;" ::: "memory");
    __syncthreads();
    out[O_ENC + (size_t)n0 * Kc + biA] = 1.0f;
    out[O_ENC + (size_t)n1 * Kc + biB] = 1.0f;

    // ---- Phase 7: block-reduce squared error; last block finalizes the loss
#pragma unroll
    for (int o = 16; o > 0; o >>= 1) acc += __shfl_down_sync(0xFFFFFFFFu, acc, o);
    if ((tid & 31) == 0) sRed[tid >> 5] = acc;
    __syncthreads();
    if (tid == 0) {
        float v = 0.0f;
#pragma unroll
        for (int w = 0; w < TPB / 32; w++) v += sRed[w];
        atomicAdd(&g_sum, v);
        __threadfence();
        unsigned t = atomicAdd(&g_count, 1u);
        sLast = (t == NBLK - 1) ? 1 : 0;
    }
    __syncthreads();
    if (sLast && tid == 0) {
        float tot = *((volatile float*)&g_sum);
        float m = tot / (float)((size_t)Nc * Dc);
        m = fminf(fmaxf(m, 0.0f), 10.0f);
        out[0] = 1.25f * m;      // q_latent + BETA * e_latent (identical forward)
        g_sum = 0.0f;            // reset for next graph replay
        g_count = 0u;
    }
}

extern "C" void kernel_launch(void* const* d_in, const int* in_sizes, int n_in,
                              void* d_out, int out_size)
{
    const float* x  = (const float*)d_in[0];
    const float* ew = (const float*)d_in[1];
    float* out = (float*)d_out;

    vq_main_kernel<<<NBLK, TPB>>>(x, ew, out);
}

// round 5
// speedup vs baseline: 1.5139x; 1.0566x over previous
#include <cuda_runtime.h>
#include <stdint.h>

// Problem constants (fixed shapes from reference)
#define Kc   512               // codebook size
#define Dc   8                 // embedding dim / channels
#define Sc   110592            // 48*48*48
#define Bc   2                 // batch
#define Nc   (Bc * Sc)         // 221184 voxels
#define TPB  384               // threads per block (12 warps)
#define VPB  768               // voxels per block (2 per thread)
#define NBLK (Nc / VPB)        // 288 blocks  (one wave @ 2 CTAs/SM)
#define NPAIR 256              // codebook pairs (Kc/2)
#define O_OUT 1                // out tensor offset (after scalar loss)
#define O_ENC (1 + Nc * Dc)    // encodings offset = 1769473
#define TILE_ENC (VPB * Kc)    // 393216 floats (1.5 MB) per block's tile
#define ZBUF_BYTES 65536       // 64 KB smem zero buffer -> 24 bulk copies/CTA

// dynamic smem layout
#define SM_ZERO  0
#define SM_EP    (ZBUF_BYTES)                    // 16384 B pair-packed codebook
#define SM_E2    (ZBUF_BYTES + 16384)            // 2048 B entry sums of squares
#define SM_RED   (ZBUF_BYTES + 16384 + 2048)     // 12 floats
#define SM_LAST  (SM_RED + 64)
#define SMEM_TOTAL (SM_LAST + 64)

__device__ float    g_sum   = 0.0f;   // reset by last block each run
__device__ unsigned g_count = 0u;

// ---- packed f32x2 helpers (per-lane rounding identical to scalar chain) ----
__device__ __forceinline__ unsigned long long pk2(float lo, float hi) {
    unsigned long long r;
    asm("mov.b64 %0, {%1, %2};" : "=l"(r) : "f"(lo), "f"(hi));
    return r;
}
__device__ __forceinline__ unsigned long long mul2(unsigned long long a, unsigned long long b) {
    unsigned long long d;
    asm("mul.rn.f32x2 %0, %1, %2;" : "=l"(d) : "l"(a), "l"(b));
    return d;
}
__device__ __forceinline__ unsigned long long add2(unsigned long long a, unsigned long long b) {
    unsigned long long d;
    asm("add.rn.f32x2 %0, %1, %2;" : "=l"(d) : "l"(a), "l"(b));
    return d;
}
__device__ __forceinline__ unsigned long long fma2(unsigned long long a, unsigned long long b, unsigned long long c) {
    unsigned long long d;
    asm("fma.rn.f32x2 %0, %1, %2, %3;" : "=l"(d) : "l"(a), "l"(b), "l"(c));
    return d;
}
__device__ __forceinline__ void upk2(unsigned long long v, float& lo, float& hi) {
    asm("mov.b64 {%0, %1}, %2;" : "=f"(lo), "=f"(hi) : "l"(v));
}
__device__ __forceinline__ uint32_t smem_u32(const void* p) {
    uint32_t a;
    asm("{ .reg .u64 t; cvta.to.shared.u64 t, %1; cvt.u32.u64 %0, t; }" : "=r"(a) : "l"(p));
    return a;
}

__global__ __launch_bounds__(TPB, 2) void vq_main_kernel(
    const float* __restrict__ x,
    const float* __restrict__ ew,
    float* __restrict__ out)
{
    extern __shared__ char smem[];
    float4*     sZero = (float4*)(smem + SM_ZERO);
    ulonglong2* sEp   = (ulonglong2*)(smem + SM_EP);   // pair-interleaved codebook
    float*      sE2   = (float*)(smem + SM_E2);
    float*      sRed  = (float*)(smem + SM_RED);
    int*        sLast = (int*)(smem + SM_LAST);

    const int tid = threadIdx.x;

    // ---- Phase 0: fill 64 KB zero buffer (TMA source)
    {
        float4 z4 = make_float4(0.f, 0.f, 0.f, 0.f);
        for (int i = tid; i < ZBUF_BYTES / 16; i += TPB) sZero[i] = z4;
    }

    // ---- Phase 1a: build pair-packed codebook: pair p, coord c -> (e[2p][c], e[2p+1][c])
    {
        float* sf = (float*)sEp;
        for (int idx = tid; idx < NPAIR * Dc; idx += TPB) {
            int p = idx >> 3, c = idx & 7;
            float lo = ew[(2 * p) * Dc + c];
            float hi = ew[(2 * p + 1) * Dc + c];
            int base = p * 16 + (c >> 1) * 4 + (c & 1) * 2;
            sf[base]     = lo;
            sf[base + 1] = hi;
        }
    }
    // ---- Phase 1b: per-entry sum of squares, sequential fp32 (match jnp.sum(e**2))
    for (int k = tid; k < Kc; k += TPB) {
        float4 a = *(const float4*)(ew + (size_t)k * Dc);
        float4 b = *(const float4*)(ew + (size_t)k * Dc + 4);
        float s = __fmul_rn(a.x, a.x);
        s = __fadd_rn(s, __fmul_rn(a.y, a.y));
        s = __fadd_rn(s, __fmul_rn(a.z, a.z));
        s = __fadd_rn(s, __fmul_rn(a.w, a.w));
        s = __fadd_rn(s, __fmul_rn(b.x, b.x));
        s = __fadd_rn(s, __fmul_rn(b.y, b.y));
        s = __fadd_rn(s, __fmul_rn(b.z, b.z));
        s = __fadd_rn(s, __fmul_rn(b.w, b.w));
        sE2[k] = s;
    }
    // Make the generic-proxy smem zero writes visible to the async (TMA) proxy.
    asm volatile("fence.proxy.async.shared::cta;" ::: "memory");
    __syncthreads();

    // ---- Phase 2: zero-fill this block's 1.5 MB encodings tile: 24 x 64 KB bulk
    // copies, spread over the first 8 lanes of warp 0 (3 each).
    float* t0 = out + O_ENC + (size_t)blockIdx.x * TILE_ENC;
    const int head = (int)(((16u - (unsigned)(((uintptr_t)t0) & 15u)) & 15u) >> 2);
    if (tid < head) t0[tid] = 0.0f;                     // peel to 16B alignment
    const int nfl = (TILE_ENC - head) & ~3;             // floats covered by TMA
    const size_t nbytes = (size_t)nfl * 4;
    if (tid < 8) {
        uint32_t s_addr = smem_u32(sZero);
        char* g = (char*)(t0 + head);
        for (size_t off = (size_t)tid * ZBUF_BYTES; off < nbytes;
             off += (size_t)8 * ZBUF_BYTES) {
            unsigned sz = (unsigned)((nbytes - off) < (size_t)ZBUF_BYTES
                                     ? (nbytes - off) : (size_t)ZBUF_BYTES);
            asm volatile(
                "cp.async.bulk.global.shared::cta.bulk_group [%0], [%1], %2;"
                :: "l"(g + off), "r"(s_addr), "r"(sz) : "memory");
        }
        asm volatile("cp.async.bulk.commit_group;" ::: "memory");
    }
    {   // tail floats not covered by 16B-granular TMA
        int done = head + nfl;
        if (tid < TILE_ENC - done) t0[done + tid] = 0.0f;
    }

    // ---- Phase 3: load this thread's two voxels (strided, warp-coalesced)
    const int bb = (blockIdx.x * VPB) >= Sc ? 1 : 0;    // batch split is block-aligned
    const int n0 = blockIdx.x * VPB + tid;
    const int n1 = n0 + TPB;
    const int sA = n0 - bb * Sc;
    const int sB = n1 - bb * Sc;
    const float* xbase = x + (size_t)bb * (Dc * Sc);

    float xA[8], xB[8];
#pragma unroll
    for (int c = 0; c < 8; c++) {
        xA[c] = xbase[(size_t)c * Sc + sA];
        xB[c] = xbase[(size_t)c * Sc + sB];
    }
    unsigned long long xa[8], xb[8];
#pragma unroll
    for (int c = 0; c < 8; c++) { xa[c] = pk2(xA[c], xA[c]); xb[c] = pk2(xB[c], xB[c]); }

    float s2A = __fmul_rn(xA[0], xA[0]);
    float s2B = __fmul_rn(xB[0], xB[0]);
#pragma unroll
    for (int c = 1; c < 8; c++) {
        s2A = __fadd_rn(s2A, __fmul_rn(xA[c], xA[c]));
        s2B = __fadd_rn(s2B, __fmul_rn(xB[c], xB[c]));
    }
    const unsigned long long sA2 = pk2(s2A, s2A);
    const unsigned long long sB2 = pk2(s2B, s2B);
    const unsigned long long n2  = pk2(-2.0f, -2.0f);

    // ---- Phase 4: argmin over 256 pairs (pure FMA loop; TMA drains under it).
    // Per lane: d = fma(-2, dot, add(sumx2, sE2[k])) — bit-identical to the
    // reference rounding, strict < gives lowest index on ties.
    float bestA = 3.4e38f, bestB = 3.4e38f;
    int   biA = 0, biB = 0;

#pragma unroll 2
    for (int p = 0; p < NPAIR; p++) {
        ulonglong2 v0 = sEp[p * 4 + 0];
        ulonglong2 v1 = sEp[p * 4 + 1];
        ulonglong2 v2 = sEp[p * 4 + 2];
        ulonglong2 v3 = sEp[p * 4 + 3];

        unsigned long long tA = mul2(xa[0], v0.x);
        unsigned long long tB = mul2(xb[0], v0.x);
        tA = fma2(xa[1], v0.y, tA);  tB = fma2(xb[1], v0.y, tB);
        tA = fma2(xa[2], v1.x, tA);  tB = fma2(xb[2], v1.x, tB);
        tA = fma2(xa[3], v1.y, tA);  tB = fma2(xb[3], v1.y, tB);
        tA = fma2(xa[4], v2.x, tA);  tB = fma2(xb[4], v2.x, tB);
        tA = fma2(xa[5], v2.y, tA);  tB = fma2(xb[5], v2.y, tB);
        tA = fma2(xa[6], v3.x, tA);  tB = fma2(xb[6], v3.x, tB);
        tA = fma2(xa[7], v3.y, tA);  tB = fma2(xb[7], v3.y, tB);

        unsigned long long e2 = *(const unsigned long long*)&sE2[2 * p];
        unsigned long long dA = fma2(n2, tA, add2(sA2, e2));
        unsigned long long dB = fma2(n2, tB, add2(sB2, e2));

        float dAl, dAh, dBl, dBh;
        upk2(dA, dAl, dAh);
        upk2(dB, dBl, dBh);
        if (dAl < bestA) { bestA = dAl; biA = 2 * p; }
        if (dAh < bestA) { bestA = dAh; biA = 2 * p + 1; }
        if (dBl < bestB) { bestB = dBl; biB = 2 * p; }
        if (dBh < bestB) { bestB = dBh; biB = 2 * p + 1; }
    }

    // ---- Phase 5: gather chosen entries, write quantized out, accumulate MSE
    const float* sf = (const float*)sEp;
    float acc = 0.0f;
    {
        int p = biA >> 1, l = biA & 1;
        float* op = out + O_OUT + (size_t)bb * (Dc * Sc) + sA;
#pragma unroll
        for (int c = 0; c < 8; c++) {
            float q = sf[p * 16 + (c >> 1) * 4 + (c & 1) * 2 + l];
            op[(size_t)c * Sc] = q;
            float dd = xA[c] - q;
            acc = fmaf(dd, dd, acc);
        }
    }
    {
        int p = biB >> 1, l = biB & 1;
        float* op = out + O_OUT + (size_t)bb * (Dc * Sc) + sB;
#pragma unroll
        for (int c = 0; c < 8; c++) {
            float q = sf[p * 16 + (c >> 1) * 4 + (c & 1) * 2 + l];
            op[(size_t)c * Sc] = q;
            float dd = xB[c] - q;
            acc = fmaf(dd, dd, acc);
        }
    }

    // ---- Phase 6: wait for the TMA zero-fill, then scatter the 1.0s (WAW safe)
    if (tid < 8) asm volatile("cp.async.bulk.wait_group 0;" ::: "memory");
    __syncthreads();
    out[O_ENC + (size_t)n0 * Kc + biA] = 1.0f;
    out[O_ENC + (size_t)n1 * Kc + biB] = 1.0f;

    // ---- Phase 7: block-reduce squared error; last block finalizes the loss
#pragma unroll
    for (int o = 16; o > 0; o >>= 1) acc += __shfl_down_sync(0xFFFFFFFFu, acc, o);
    if ((tid & 31) == 0) sRed[tid >> 5] = acc;
    __syncthreads();
    if (tid == 0) {
        float v = 0.0f;
#pragma unroll
        for (int w = 0; w < TPB / 32; w++) v += sRed[w];
        atomicAdd(&g_sum, v);
        __threadfence();
        unsigned t = atomicAdd(&g_count, 1u);
        *sLast = (t == NBLK - 1) ? 1 : 0;
    }
    __syncthreads();
    if (*sLast && tid == 0) {
        float tot = *((volatile float*)&g_sum);
        float m = tot / (float)((size_t)Nc * Dc);
        m = fminf(fmaxf(m, 0.0f), 10.0f);
        out[0] = 1.25f * m;      // q_latent + BETA * e_latent (identical forward)
        g_sum = 0.0f;            // reset for next graph replay
        g_count = 0u;
    }
}

extern "C" void kernel_launch(void* const* d_in, const int* in_sizes, int n_in,
                              void* d_out, int out_size)
{
    const float* x  = (const float*)d_in[0];
    const float* ew = (const float*)d_in[1];
    float* out = (float*)d_out;

    cudaFuncSetAttribute(vq_main_kernel,
                         cudaFuncAttributeMaxDynamicSharedMemorySize, SMEM_TOTAL);
    vq_main_kernel<<<NBLK, TPB, SMEM_TOTAL>>>(x, ew, out);
}